// round 14
// baseline (speedup 1.0000x reference)
#include <cuda_runtime.h>

#define H 8192
#define T 64
#define NBLK 512            // persistent grid: 512 blocks x 512 threads, 16 rows/block

// ---- __device__ scratch (no allocations allowed) ----
__device__ float g_pre[T * H];                              // 2 MB
__device__ signed char g_Whi[(size_t)H * H];                // 64 MB hi bytes (q>>4)
__device__ unsigned char g_Wlo[(size_t)H * H / 2];          // 32 MB lo nibbles
__device__ float g_scale[H];                                // rowmax/(2047*32767)
__device__ __align__(16) short g_hq[2][H];                  // int16 h double buffer
__device__ unsigned g_bar;                                  // grid barrier counter

// ---------------------------------------------------------------------------
// f32x2 helpers
// ---------------------------------------------------------------------------
__device__ __forceinline__ void ffma2(unsigned long long& d,
                                      unsigned long long a,
                                      unsigned long long b)
{
    asm("fma.rn.f32x2 %0, %1, %2, %3;" : "=l"(d) : "l"(a), "l"(b), "l"(d));
}
__device__ __forceinline__ unsigned long long dup2(float a)
{
    unsigned long long r;
    asm("mov.b64 %0, {%1, %1};" : "=l"(r) : "r"(__float_as_int(a)));
    return r;
}
__device__ __forceinline__ float2 unpack2(unsigned long long v)
{
    float2 f;
    f.x = __int_as_float((int)(v & 0xffffffffu));
    f.y = __int_as_float((int)(v >> 32));
    return f;
}

// ---------------------------------------------------------------------------
// Fused prologue: blocks [0,128) do the x@W_ih^T GEMM tile; blocks [128,8320)
// quantize one W_hh row each. FMA-bound GEMM overlaps DRAM-bound quant.
// ---------------------------------------------------------------------------
__global__ __launch_bounds__(256) void prologue_kernel(
    const float* __restrict__ x,
    const float* __restrict__ Wih,
    const float* __restrict__ b,
    const float* __restrict__ Whh)
{
    __shared__ float As[16][64];
    __shared__ float Bs[16][64];
    __shared__ float red[8];

    int tid = threadIdx.x;

    if (blockIdx.x < 128) {
        // ---------------- GEMM tile ----------------
        if (blockIdx.x == 0 && tid == 0) g_bar = 0;   // reset grid barrier

        const int BK = 16;
        int n0  = blockIdx.x * 64;
        int tx  = tid & 15;
        int ty  = tid >> 4;
        int lr  = tid >> 2;
        int lk  = (tid & 3) * 4;

        unsigned long long acc[4][2];
        #pragma unroll
        for (int i = 0; i < 4; i++) { acc[i][0] = 0ull; acc[i][1] = 0ull; }

        for (int k0 = 0; k0 < H; k0 += BK) {
            float4 av = *(const float4*)(x + (size_t)lr * H + k0 + lk);
            float4 bv = *(const float4*)(Wih + (size_t)(n0 + lr) * H + k0 + lk);
            __syncthreads();
            As[lk + 0][lr] = av.x; As[lk + 1][lr] = av.y;
            As[lk + 2][lr] = av.z; As[lk + 3][lr] = av.w;
            Bs[lk + 0][lr] = bv.x; Bs[lk + 1][lr] = bv.y;
            Bs[lk + 2][lr] = bv.z; Bs[lk + 3][lr] = bv.w;
            __syncthreads();

            #pragma unroll
            for (int kk = 0; kk < BK; kk++) {
                float4 af = *(const float4*)&As[kk][ty * 4];
                ulonglong2 bb = *(const ulonglong2*)&Bs[kk][tx * 4];
                unsigned long long am[4] = { dup2(af.x), dup2(af.y),
                                             dup2(af.z), dup2(af.w) };
                #pragma unroll
                for (int i = 0; i < 4; i++) {
                    ffma2(acc[i][0], am[i], bb.x);
                    ffma2(acc[i][1], am[i], bb.y);
                }
            }
        }

        #pragma unroll
        for (int i = 0; i < 4; i++) {
            int m = ty * 4 + i;
            #pragma unroll
            for (int j = 0; j < 2; j++) {
                int n = n0 + tx * 4 + 2 * j;
                float2 p = unpack2(acc[i][j]);
                p.x += b[n];
                p.y += b[n + 1];
                *(float2*)&g_pre[(size_t)m * H + n] = p;
            }
        }
    } else {
        // ---------------- quantize one W_hh row ----------------
        int row = blockIdx.x - 128;
        const float4* w4 = (const float4*)(Whh + (size_t)row * H);

        float4 va[4], vb[4];
        float m = 0.f;
        #pragma unroll
        for (int k = 0; k < 4; k++) {
            int g = tid + k * 256;          // 8-weight group index 0..1023
            va[k] = w4[2 * g];
            vb[k] = w4[2 * g + 1];
            m = fmaxf(m, fmaxf(fmaxf(fabsf(va[k].x), fabsf(va[k].y)),
                               fmaxf(fabsf(va[k].z), fabsf(va[k].w))));
            m = fmaxf(m, fmaxf(fmaxf(fabsf(vb[k].x), fabsf(vb[k].y)),
                               fmaxf(fabsf(vb[k].z), fabsf(vb[k].w))));
        }
        #pragma unroll
        for (int o = 16; o; o >>= 1)
            m = fmaxf(m, __shfl_xor_sync(0xffffffffu, m, o));
        if ((tid & 31) == 0) red[tid >> 5] = m;
        __syncthreads();
        float rowmax = fmaxf(fmaxf(fmaxf(red[0], red[1]), fmaxf(red[2], red[3])),
                             fmaxf(fmaxf(red[4], red[5]), fmaxf(red[6], red[7])));
        rowmax = fmaxf(rowmax, 1e-30f);
        float inv = 2047.0f / rowmax;

        uint2*    hi2 = (uint2*)(g_Whi + (size_t)row * H);
        unsigned* lo4 = (unsigned*)(g_Wlo + (size_t)row * (H / 2));

        #pragma unroll
        for (int k = 0; k < 4; k++) {
            int g = tid + k * 256;
            int q[8];
            q[0] = max(-2047, min(2047, __float2int_rn(va[k].x * inv)));
            q[1] = max(-2047, min(2047, __float2int_rn(va[k].y * inv)));
            q[2] = max(-2047, min(2047, __float2int_rn(va[k].z * inv)));
            q[3] = max(-2047, min(2047, __float2int_rn(va[k].w * inv)));
            q[4] = max(-2047, min(2047, __float2int_rn(vb[k].x * inv)));
            q[5] = max(-2047, min(2047, __float2int_rn(vb[k].y * inv)));
            q[6] = max(-2047, min(2047, __float2int_rn(vb[k].z * inv)));
            q[7] = max(-2047, min(2047, __float2int_rn(vb[k].w * inv)));

            unsigned w0 = ((unsigned)((q[0] >> 4) & 0xFF))
                        | ((unsigned)((q[1] >> 4) & 0xFF) << 8)
                        | ((unsigned)((q[2] >> 4) & 0xFF) << 16)
                        | ((unsigned)((q[3] >> 4) & 0xFF) << 24);
            unsigned w1 = ((unsigned)((q[4] >> 4) & 0xFF))
                        | ((unsigned)((q[5] >> 4) & 0xFF) << 8)
                        | ((unsigned)((q[6] >> 4) & 0xFF) << 16)
                        | ((unsigned)((q[7] >> 4) & 0xFF) << 24);
            unsigned lw = (unsigned)(q[0] & 15)
                        | ((unsigned)(q[4] & 15) << 4)
                        | ((unsigned)(q[1] & 15) << 8)
                        | ((unsigned)(q[5] & 15) << 12)
                        | ((unsigned)(q[2] & 15) << 16)
                        | ((unsigned)(q[6] & 15) << 20)
                        | ((unsigned)(q[3] & 15) << 24)
                        | ((unsigned)(q[7] & 15) << 28);
            hi2[g] = make_uint2(w0, w1);
            lo4[g] = lw;
        }
        if (tid == 0) g_scale[row] = rowmax / (2047.0f * 32767.0f);
    }
}

// ---------------------------------------------------------------------------
// dp2a inner loop shared by both recurrence kernels.
// ---------------------------------------------------------------------------
__device__ __forceinline__ float gemv_row_dot(
    const uint4* __restrict__ hi4, const uint2* __restrict__ lo2,
    const uint4* __restrict__ shA, const uint4* __restrict__ shB, int lane)
{
    int accH = 0, accL = 0;
    #pragma unroll 4
    for (int i = lane; i < H / 16; i += 32) {     // 16 iters, 16 weights each
        uint4 hw = hi4[i];
        uint2 lwv = lo2[i];
        uint4 ha = shA[i];
        uint4 hb = shB[i];

        unsigned a0 = lwv.x & 0x0F0F0F0Fu, a1 = (lwv.x >> 4) & 0x0F0F0F0Fu;
        unsigned c0 = lwv.y & 0x0F0F0F0Fu, c1 = (lwv.y >> 4) & 0x0F0F0F0Fu;

        asm("dp2a.lo.s32.s32 %0, %1, %2, %0;" : "+r"(accH) : "r"(ha.x), "r"(hw.x));
        asm("dp2a.hi.s32.s32 %0, %1, %2, %0;" : "+r"(accH) : "r"(ha.y), "r"(hw.x));
        asm("dp2a.lo.s32.s32 %0, %1, %2, %0;" : "+r"(accH) : "r"(ha.z), "r"(hw.y));
        asm("dp2a.hi.s32.s32 %0, %1, %2, %0;" : "+r"(accH) : "r"(ha.w), "r"(hw.y));
        asm("dp2a.lo.s32.s32 %0, %1, %2, %0;" : "+r"(accH) : "r"(hb.x), "r"(hw.z));
        asm("dp2a.hi.s32.s32 %0, %1, %2, %0;" : "+r"(accH) : "r"(hb.y), "r"(hw.z));
        asm("dp2a.lo.s32.s32 %0, %1, %2, %0;" : "+r"(accH) : "r"(hb.z), "r"(hw.w));
        asm("dp2a.hi.s32.s32 %0, %1, %2, %0;" : "+r"(accH) : "r"(hb.w), "r"(hw.w));

        asm("dp2a.lo.s32.u32 %0, %1, %2, %0;" : "+r"(accL) : "r"(ha.x), "r"(a0));
        asm("dp2a.hi.s32.u32 %0, %1, %2, %0;" : "+r"(accL) : "r"(ha.y), "r"(a0));
        asm("dp2a.lo.s32.u32 %0, %1, %2, %0;" : "+r"(accL) : "r"(ha.z), "r"(a1));
        asm("dp2a.hi.s32.u32 %0, %1, %2, %0;" : "+r"(accL) : "r"(ha.w), "r"(a1));
        asm("dp2a.lo.s32.u32 %0, %1, %2, %0;" : "+r"(accL) : "r"(hb.x), "r"(c0));
        asm("dp2a.hi.s32.u32 %0, %1, %2, %0;" : "+r"(accL) : "r"(hb.y), "r"(c0));
        asm("dp2a.lo.s32.u32 %0, %1, %2, %0;" : "+r"(accL) : "r"(hb.z), "r"(c1));
        asm("dp2a.hi.s32.u32 %0, %1, %2, %0;" : "+r"(accL) : "r"(hb.w), "r"(c1));
    }
    return fmaf(16.0f, (float)accH, (float)accL);
}

// ---------------------------------------------------------------------------
// Persistent recurrence: one launch, all T steps, software grid barrier.
// 512 blocks x 512 threads, 4 CTAs/SM -> single co-resident wave (host-checked).
// ---------------------------------------------------------------------------
__global__ __launch_bounds__(512, 4) void gemv_persistent_kernel(
    float* __restrict__ out)
{
    __shared__ uint4 shA[H / 16];
    __shared__ uint4 shB[H / 16];

    int tid  = threadIdx.x;
    int bid  = blockIdx.x;
    int warp = tid >> 5;
    int lane = tid & 31;
    int row  = bid * 16 + warp;

    // ---- step 0: h = tanh(pre[0]) for this block's 16 rows ----
    if (tid < 16) {
        int r = bid * 16 + tid;
        float h = tanhf(g_pre[r]);
        out[r] = h;
        g_hq[0][r] = (short)__float2int_rn(h * 32767.0f);
    }

    const uint4* hi4 = (const uint4*)(g_Whi + (size_t)row * H);
    const uint2* lo2 = (const uint2*)(g_Wlo + (size_t)row * (H / 2));
    float scale = g_scale[row];

    for (int t = 1; t < T; t++) {
        // ---- grid barrier: wait until all blocks finished step t-1 ----
        __syncthreads();
        if (tid == 0) {
            asm volatile("red.release.gpu.global.add.u32 [%0], 1;"
                         :: "l"(&g_bar) : "memory");
            unsigned v, target = (unsigned)NBLK * (unsigned)t;
            do {
                asm volatile("ld.acquire.gpu.global.u32 %0, [%1];"
                             : "=r"(v) : "l"(&g_bar));
                if (v < target) __nanosleep(64);
            } while (v < target);
        }
        __syncthreads();

        // ---- stage h_{t-1} in smem (even/odd split, conflict-free) ----
        const uint4* hq4 = (const uint4*)g_hq[(t - 1) & 1];
        #pragma unroll
        for (int k = 0; k < 2; k++) {
            int j = tid + k * 512;
            uint4 v = hq4[j];
            if (j & 1) shB[j >> 1] = v; else shA[j >> 1] = v;
        }
        __syncthreads();

        float acc = gemv_row_dot(hi4, lo2, shA, shB, lane);
        #pragma unroll
        for (int o = 16; o; o >>= 1)
            acc += __shfl_xor_sync(0xffffffffu, acc, o);

        if (lane == 0) {
            float h = tanhf(acc * scale + g_pre[t * H + row]);
            out[(size_t)t * H + row] = h;
            g_hq[t & 1][row] = (short)__float2int_rn(h * 32767.0f);
        }
    }
}

// ---------------------------------------------------------------------------
// Fallback path (per-step launches) — proven correct in prior rounds.
// ---------------------------------------------------------------------------
__global__ void step0_kernel(float* __restrict__ out)
{
    int i = blockIdx.x * blockDim.x + threadIdx.x;
    float h = tanhf(g_pre[i]);
    out[i] = h;
    g_hq[0][i] = (short)__float2int_rn(h * 32767.0f);
}

__global__ __launch_bounds__(512) void gemv_q_kernel(
    float* __restrict__ h_out, int t)
{
    __shared__ uint4 shA[H / 16];
    __shared__ uint4 shB[H / 16];

    int tid = threadIdx.x;
    const uint4* hq4 = (const uint4*)g_hq[(t - 1) & 1];
    #pragma unroll
    for (int k = 0; k < 2; k++) {
        int j = tid + k * 512;
        uint4 v = hq4[j];
        if (j & 1) shB[j >> 1] = v; else shA[j >> 1] = v;
    }
    __syncthreads();

    int warp = tid >> 5;
    int lane = tid & 31;
    int row  = blockIdx.x * 16 + warp;

    const uint4* hi4 = (const uint4*)(g_Whi + (size_t)row * H);
    const uint2* lo2 = (const uint2*)(g_Wlo + (size_t)row * (H / 2));

    float acc = gemv_row_dot(hi4, lo2, shA, shB, lane);
    #pragma unroll
    for (int o = 16; o; o >>= 1)
        acc += __shfl_xor_sync(0xffffffffu, acc, o);

    if (lane == 0) {
        float h = tanhf(acc * g_scale[row] + g_pre[t * H + row]);
        h_out[row] = h;
        g_hq[t & 1][row] = (short)__float2int_rn(h * 32767.0f);
    }
}

// ---------------------------------------------------------------------------
extern "C" void kernel_launch(void* const* d_in, const int* in_sizes, int n_in,
                              void* d_out, int out_size)
{
    const float* x    = (const float*)d_in[0];   // (64, 8192)
    const float* W_ih = (const float*)d_in[1];   // (8192, 8192)
    const float* W_hh = (const float*)d_in[2];   // (8192, 8192)
    const float* b    = (const float*)d_in[3];   // (8192,)
    float* out = (float*)d_out;                  // (64*8192,) fp32

    (void)in_sizes; (void)n_in; (void)out_size;

    prologue_kernel<<<128 + H, 256>>>(x, W_ih, b, W_hh);

    // Persistent path requires all NBLK blocks co-resident (software barrier).
    int maxb = 0, sms = 0, dev = 0;
    cudaGetDevice(&dev);
    cudaOccupancyMaxActiveBlocksPerMultiprocessor(
        &maxb, gemv_persistent_kernel, 512, 0);
    cudaDeviceGetAttribute(&sms, cudaDevAttrMultiProcessorCount, dev);

    if (maxb * sms >= NBLK) {
        gemv_persistent_kernel<<<NBLK, 512>>>(out);
    } else {
        step0_kernel<<<H / 256, 256>>>(out);
        for (int t = 1; t < T; t++)
            gemv_q_kernel<<<H / 16, 512>>>(out + (size_t)t * H, t);
    }
}

// round 16
// speedup vs baseline: 1.1603x; 1.1603x over previous
#include <cuda_runtime.h>

#define H 8192
#define T 64
#define NBLK 512            // persistent grid: 512 blocks x 512 threads, 16 rows/block

// ---- __device__ scratch (no allocations allowed) ----
__device__ float g_pre[T * H];                              // 2 MB
__device__ signed char g_Whi[(size_t)H * H];                // 64 MB hi bytes (q>>4)
__device__ unsigned char g_Wlo[(size_t)H * H / 2];          // 32 MB lo nibbles
__device__ float g_scale[H];                                // rowmax/(2047*32767)
__device__ __align__(16) short g_hq[2][H];                  // int16 h double buffer
__device__ unsigned g_bar;                                  // grid barrier counter

// ---------------------------------------------------------------------------
// f32x2 helpers
// ---------------------------------------------------------------------------
__device__ __forceinline__ void ffma2(unsigned long long& d,
                                      unsigned long long a,
                                      unsigned long long b)
{
    asm("fma.rn.f32x2 %0, %1, %2, %3;" : "=l"(d) : "l"(a), "l"(b), "l"(d));
}
__device__ __forceinline__ unsigned long long dup2(float a)
{
    unsigned long long r;
    asm("mov.b64 %0, {%1, %1};" : "=l"(r) : "r"(__float_as_int(a)));
    return r;
}
__device__ __forceinline__ float2 unpack2(unsigned long long v)
{
    float2 f;
    f.x = __int_as_float((int)(v & 0xffffffffu));
    f.y = __int_as_float((int)(v >> 32));
    return f;
}

// ---------------------------------------------------------------------------
// GEMM: pre = x @ W_ih^T + b.  Dedicated kernel (proven ~130us).
// Also resets the grid barrier for the persistent kernel.
// ---------------------------------------------------------------------------
__global__ __launch_bounds__(256) void gemm_pre_kernel(
    const float* __restrict__ x,
    const float* __restrict__ W,
    const float* __restrict__ b)
{
    const int BN = 64, BK = 16;
    __shared__ float As[BK][64];
    __shared__ float Bs[BK][BN];

    int tid = threadIdx.x;
    if (blockIdx.x == 0 && tid == 0) g_bar = 0;   // reset for persistent kernel

    int n0  = blockIdx.x * BN;
    int tx  = tid & 15;
    int ty  = tid >> 4;
    int lr  = tid >> 2;
    int lk  = (tid & 3) * 4;

    unsigned long long acc[4][2];
    #pragma unroll
    for (int i = 0; i < 4; i++) { acc[i][0] = 0ull; acc[i][1] = 0ull; }

    for (int k0 = 0; k0 < H; k0 += BK) {
        float4 av = *(const float4*)(x + (size_t)lr * H + k0 + lk);
        float4 bv = *(const float4*)(W + (size_t)(n0 + lr) * H + k0 + lk);
        __syncthreads();
        As[lk + 0][lr] = av.x; As[lk + 1][lr] = av.y;
        As[lk + 2][lr] = av.z; As[lk + 3][lr] = av.w;
        Bs[lk + 0][lr] = bv.x; Bs[lk + 1][lr] = bv.y;
        Bs[lk + 2][lr] = bv.z; Bs[lk + 3][lr] = bv.w;
        __syncthreads();

        #pragma unroll
        for (int kk = 0; kk < BK; kk++) {
            float4 af = *(const float4*)&As[kk][ty * 4];
            ulonglong2 bb = *(const ulonglong2*)&Bs[kk][tx * 4];
            unsigned long long am[4] = { dup2(af.x), dup2(af.y),
                                         dup2(af.z), dup2(af.w) };
            #pragma unroll
            for (int i = 0; i < 4; i++) {
                ffma2(acc[i][0], am[i], bb.x);
                ffma2(acc[i][1], am[i], bb.y);
            }
        }
    }

    #pragma unroll
    for (int i = 0; i < 4; i++) {
        int m = ty * 4 + i;
        #pragma unroll
        for (int j = 0; j < 2; j++) {
            int n = n0 + tx * 4 + 2 * j;
            float2 p = unpack2(acc[i][j]);
            p.x += b[n];
            p.y += b[n + 1];
            *(float2*)&g_pre[(size_t)m * H + n] = p;
        }
    }
}

// ---------------------------------------------------------------------------
// Pack helper: quantize one 8-weight group to (hi uint2, lo uint) dp2a layout.
// ---------------------------------------------------------------------------
__device__ __forceinline__ void pack_group(float4 va, float4 vb, float inv,
                                           uint2& hw, unsigned& lw)
{
    int q[8];
    q[0] = max(-2047, min(2047, __float2int_rn(va.x * inv)));
    q[1] = max(-2047, min(2047, __float2int_rn(va.y * inv)));
    q[2] = max(-2047, min(2047, __float2int_rn(va.z * inv)));
    q[3] = max(-2047, min(2047, __float2int_rn(va.w * inv)));
    q[4] = max(-2047, min(2047, __float2int_rn(vb.x * inv)));
    q[5] = max(-2047, min(2047, __float2int_rn(vb.y * inv)));
    q[6] = max(-2047, min(2047, __float2int_rn(vb.z * inv)));
    q[7] = max(-2047, min(2047, __float2int_rn(vb.w * inv)));

    hw.x = ((unsigned)((q[0] >> 4) & 0xFF))
         | ((unsigned)((q[1] >> 4) & 0xFF) << 8)
         | ((unsigned)((q[2] >> 4) & 0xFF) << 16)
         | ((unsigned)((q[3] >> 4) & 0xFF) << 24);
    hw.y = ((unsigned)((q[4] >> 4) & 0xFF))
         | ((unsigned)((q[5] >> 4) & 0xFF) << 8)
         | ((unsigned)((q[6] >> 4) & 0xFF) << 16)
         | ((unsigned)((q[7] >> 4) & 0xFF) << 24);
    lw   = (unsigned)(q[0] & 15)
         | ((unsigned)(q[4] & 15) << 4)
         | ((unsigned)(q[1] & 15) << 8)
         | ((unsigned)(q[5] & 15) << 12)
         | ((unsigned)(q[2] & 15) << 16)
         | ((unsigned)(q[6] & 15) << 20)
         | ((unsigned)(q[3] & 15) << 24)
         | ((unsigned)(q[7] & 15) << 28);
}

// ---------------------------------------------------------------------------
// dp2a inner loop.
// ---------------------------------------------------------------------------
__device__ __forceinline__ float gemv_row_dot(
    const uint4* __restrict__ hi4, const uint2* __restrict__ lo2,
    const uint4* __restrict__ shA, const uint4* __restrict__ shB, int lane)
{
    int accH = 0, accL = 0;
    #pragma unroll 4
    for (int i = lane; i < H / 16; i += 32) {     // 16 iters, 16 weights each
        uint4 hw = hi4[i];
        uint2 lwv = lo2[i];
        uint4 ha = shA[i];
        uint4 hb = shB[i];

        unsigned a0 = lwv.x & 0x0F0F0F0Fu, a1 = (lwv.x >> 4) & 0x0F0F0F0Fu;
        unsigned c0 = lwv.y & 0x0F0F0F0Fu, c1 = (lwv.y >> 4) & 0x0F0F0F0Fu;

        asm("dp2a.lo.s32.s32 %0, %1, %2, %0;" : "+r"(accH) : "r"(ha.x), "r"(hw.x));
        asm("dp2a.hi.s32.s32 %0, %1, %2, %0;" : "+r"(accH) : "r"(ha.y), "r"(hw.x));
        asm("dp2a.lo.s32.s32 %0, %1, %2, %0;" : "+r"(accH) : "r"(ha.z), "r"(hw.y));
        asm("dp2a.hi.s32.s32 %0, %1, %2, %0;" : "+r"(accH) : "r"(ha.w), "r"(hw.y));
        asm("dp2a.lo.s32.s32 %0, %1, %2, %0;" : "+r"(accH) : "r"(hb.x), "r"(hw.z));
        asm("dp2a.hi.s32.s32 %0, %1, %2, %0;" : "+r"(accH) : "r"(hb.y), "r"(hw.z));
        asm("dp2a.lo.s32.s32 %0, %1, %2, %0;" : "+r"(accH) : "r"(hb.z), "r"(hw.w));
        asm("dp2a.hi.s32.s32 %0, %1, %2, %0;" : "+r"(accH) : "r"(hb.w), "r"(hw.w));

        asm("dp2a.lo.s32.u32 %0, %1, %2, %0;" : "+r"(accL) : "r"(ha.x), "r"(a0));
        asm("dp2a.hi.s32.u32 %0, %1, %2, %0;" : "+r"(accL) : "r"(ha.y), "r"(a0));
        asm("dp2a.lo.s32.u32 %0, %1, %2, %0;" : "+r"(accL) : "r"(ha.z), "r"(a1));
        asm("dp2a.hi.s32.u32 %0, %1, %2, %0;" : "+r"(accL) : "r"(ha.w), "r"(a1));
        asm("dp2a.lo.s32.u32 %0, %1, %2, %0;" : "+r"(accL) : "r"(hb.x), "r"(c0));
        asm("dp2a.hi.s32.u32 %0, %1, %2, %0;" : "+r"(accL) : "r"(hb.y), "r"(c0));
        asm("dp2a.lo.s32.u32 %0, %1, %2, %0;" : "+r"(accL) : "r"(hb.z), "r"(c1));
        asm("dp2a.hi.s32.u32 %0, %1, %2, %0;" : "+r"(accL) : "r"(hb.w), "r"(c1));
    }
    return fmaf(16.0f, (float)accH, (float)accL);
}

// ---------------------------------------------------------------------------
// Persistent kernel: per-block quantization of its OWN 16 rows (no cross-block
// dependency -> no barrier), then step 0, then 63 barrier-synced gemv steps.
// ---------------------------------------------------------------------------
__global__ __launch_bounds__(512, 4) void gemv_persistent_kernel(
    const float* __restrict__ Whh,
    float* __restrict__ out)
{
    __shared__ uint4 shA[H / 16];
    __shared__ uint4 shB[H / 16];
    __shared__ float red[16];

    int tid  = threadIdx.x;
    int bid  = blockIdx.x;
    int warp = tid >> 5;
    int lane = tid & 31;
    int row  = bid * 16 + warp;

    // ---- Phase A: quantize this block's 16 rows (producer == consumer) ----
    for (int r = 0; r < 16; r++) {
        int qrow = bid * 16 + r;
        const float4* w4 = (const float4*)(Whh + (size_t)qrow * H);

        // pass 1: row max
        float m = 0.f;
        #pragma unroll
        for (int i = tid; i < H / 4; i += 512) {
            float4 v = w4[i];
            m = fmaxf(m, fmaxf(fmaxf(fabsf(v.x), fabsf(v.y)),
                               fmaxf(fabsf(v.z), fabsf(v.w))));
        }
        #pragma unroll
        for (int o = 16; o; o >>= 1)
            m = fmaxf(m, __shfl_xor_sync(0xffffffffu, m, o));
        if (lane == 0) red[warp] = m;
        __syncthreads();
        float rowmax = red[0];
        #pragma unroll
        for (int w = 1; w < 16; w++) rowmax = fmaxf(rowmax, red[w]);
        rowmax = fmaxf(rowmax, 1e-30f);
        float inv = 2047.0f / rowmax;

        // pass 2: pack (row is L2/L1-hot from pass 1)
        uint2*    hi2 = (uint2*)(g_Whi + (size_t)qrow * H);
        unsigned* lo4 = (unsigned*)(g_Wlo + (size_t)qrow * (H / 2));
        #pragma unroll
        for (int g = tid; g < H / 8; g += 512) {   // 2 iters
            uint2 hw; unsigned lw;
            pack_group(w4[2 * g], w4[2 * g + 1], inv, hw, lw);
            hi2[g] = hw;
            lo4[g] = lw;
        }
        if (tid == 0) g_scale[qrow] = rowmax / (2047.0f * 32767.0f);
        __syncthreads();    // red reuse + global visibility within block
    }

    // ---- step 0: h = tanh(pre[0]) for this block's 16 rows ----
    if (tid < 16) {
        int r = bid * 16 + tid;
        float h = tanhf(g_pre[r]);
        out[r] = h;
        g_hq[0][r] = (short)__float2int_rn(h * 32767.0f);
    }

    const uint4* hi4 = (const uint4*)(g_Whi + (size_t)row * H);
    const uint2* lo2 = (const uint2*)(g_Wlo + (size_t)row * (H / 2));
    float scale = g_scale[row];

    for (int t = 1; t < T; t++) {
        // ---- grid barrier: all blocks finished step t-1 ----
        __syncthreads();
        if (tid == 0) {
            asm volatile("red.release.gpu.global.add.u32 [%0], 1;"
                         :: "l"(&g_bar) : "memory");
            unsigned v, target = (unsigned)NBLK * (unsigned)t;
            do {
                asm volatile("ld.acquire.gpu.global.u32 %0, [%1];"
                             : "=r"(v) : "l"(&g_bar));
                if (v < target) __nanosleep(64);
            } while (v < target);
        }
        __syncthreads();

        // ---- stage h_{t-1} in smem (even/odd split, conflict-free) ----
        const uint4* hq4 = (const uint4*)g_hq[(t - 1) & 1];
        #pragma unroll
        for (int k = 0; k < 2; k++) {
            int j = tid + k * 512;
            uint4 v = hq4[j];
            if (j & 1) shB[j >> 1] = v; else shA[j >> 1] = v;
        }
        __syncthreads();

        float acc = gemv_row_dot(hi4, lo2, shA, shB, lane);
        #pragma unroll
        for (int o = 16; o; o >>= 1)
            acc += __shfl_xor_sync(0xffffffffu, acc, o);

        if (lane == 0) {
            float h = tanhf(acc * scale + g_pre[t * H + row]);
            out[(size_t)t * H + row] = h;
            g_hq[t & 1][row] = (short)__float2int_rn(h * 32767.0f);
        }
    }
}

// ---------------------------------------------------------------------------
// Fallback path (per-step launches) — proven correct in prior rounds.
// ---------------------------------------------------------------------------
__global__ __launch_bounds__(256) void quant_kernel(const float* __restrict__ W)
{
    __shared__ float red[8];
    int row = blockIdx.x;
    int tid = threadIdx.x;
    const float4* w4 = (const float4*)(W + (size_t)row * H);

    float m = 0.f;
    #pragma unroll
    for (int i = tid; i < H / 4; i += 256) {
        float4 v = w4[i];
        m = fmaxf(m, fmaxf(fmaxf(fabsf(v.x), fabsf(v.y)),
                           fmaxf(fabsf(v.z), fabsf(v.w))));
    }
    #pragma unroll
    for (int o = 16; o; o >>= 1)
        m = fmaxf(m, __shfl_xor_sync(0xffffffffu, m, o));
    if ((tid & 31) == 0) red[tid >> 5] = m;
    __syncthreads();
    float rowmax = fmaxf(fmaxf(fmaxf(red[0], red[1]), fmaxf(red[2], red[3])),
                         fmaxf(fmaxf(red[4], red[5]), fmaxf(red[6], red[7])));
    rowmax = fmaxf(rowmax, 1e-30f);
    float inv = 2047.0f / rowmax;

    uint2*    hi2 = (uint2*)(g_Whi + (size_t)row * H);
    unsigned* lo4 = (unsigned*)(g_Wlo + (size_t)row * (H / 2));
    for (int g = tid; g < H / 8; g += 256) {
        uint2 hw; unsigned lw;
        pack_group(w4[2 * g], w4[2 * g + 1], inv, hw, lw);
        hi2[g] = hw;
        lo4[g] = lw;
    }
    if (tid == 0) g_scale[row] = rowmax / (2047.0f * 32767.0f);
}

__global__ void step0_kernel(float* __restrict__ out)
{
    int i = blockIdx.x * blockDim.x + threadIdx.x;
    float h = tanhf(g_pre[i]);
    out[i] = h;
    g_hq[0][i] = (short)__float2int_rn(h * 32767.0f);
}

__global__ __launch_bounds__(512) void gemv_q_kernel(
    float* __restrict__ h_out, int t)
{
    __shared__ uint4 shA[H / 16];
    __shared__ uint4 shB[H / 16];

    int tid = threadIdx.x;
    const uint4* hq4 = (const uint4*)g_hq[(t - 1) & 1];
    #pragma unroll
    for (int k = 0; k < 2; k++) {
        int j = tid + k * 512;
        uint4 v = hq4[j];
        if (j & 1) shB[j >> 1] = v; else shA[j >> 1] = v;
    }
    __syncthreads();

    int warp = tid >> 5;
    int lane = tid & 31;
    int row  = blockIdx.x * 16 + warp;

    const uint4* hi4 = (const uint4*)(g_Whi + (size_t)row * H);
    const uint2* lo2 = (const uint2*)(g_Wlo + (size_t)row * (H / 2));

    float acc = gemv_row_dot(hi4, lo2, shA, shB, lane);
    #pragma unroll
    for (int o = 16; o; o >>= 1)
        acc += __shfl_xor_sync(0xffffffffu, acc, o);

    if (lane == 0) {
        float h = tanhf(acc * g_scale[row] + g_pre[t * H + row]);
        h_out[row] = h;
        g_hq[t & 1][row] = (short)__float2int_rn(h * 32767.0f);
    }
}

// ---------------------------------------------------------------------------
extern "C" void kernel_launch(void* const* d_in, const int* in_sizes, int n_in,
                              void* d_out, int out_size)
{
    const float* x    = (const float*)d_in[0];   // (64, 8192)
    const float* W_ih = (const float*)d_in[1];   // (8192, 8192)
    const float* W_hh = (const float*)d_in[2];   // (8192, 8192)
    const float* b    = (const float*)d_in[3];   // (8192,)
    float* out = (float*)d_out;                  // (64*8192,) fp32

    (void)in_sizes; (void)n_in; (void)out_size;

    gemm_pre_kernel<<<H / 64, 256>>>(x, W_ih, b);

    // Persistent path requires all NBLK blocks co-resident (software barrier).
    int maxb = 0, sms = 0, dev = 0;
    cudaGetDevice(&dev);
    cudaOccupancyMaxActiveBlocksPerMultiprocessor(
        &maxb, gemv_persistent_kernel, 512, 0);
    cudaDeviceGetAttribute(&sms, cudaDevAttrMultiProcessorCount, dev);

    if (maxb * sms >= NBLK) {
        gemv_persistent_kernel<<<NBLK, 512>>>(W_hh, out);
    } else {
        quant_kernel<<<H, 256>>>(W_hh);
        step0_kernel<<<H / 256, 256>>>(out);
        for (int t = 1; t < T; t++)
            gemv_q_kernel<<<H / 16, 512>>>(out + (size_t)t * H, t);
    }
}